// round 2
// baseline (speedup 1.0000x reference)
#include <cuda_runtime.h>

#define Bb 256
#define Tt 256
#define Cc 384
#define Hh 64
#define BT (Bb*Tt)

// Scratch for projected q, k, v: [B*T, H] each (16.8 MB each).
__device__ float g_q[BT*Hh];
__device__ float g_k[BT*Hh];
__device__ float g_v[BT*Hh];

// ---------------------------------------------------------------------------
// Kernel 1: fused q/k/v projection.
// Grid: BT/16 blocks of 256 threads. Each block computes 16 rows x 64 cols
// for all three weight matrices. x tile staged in smem; W reads are
// L2-resident (3*96KB total, shared by all blocks).
// Thread layout: h = tid & 63 (coalesced W loads), 4 rows per thread.
// ---------------------------------------------------------------------------
__global__ __launch_bounds__(256) void proj_kernel(
    const float* __restrict__ x,
    const float* __restrict__ Wq,
    const float* __restrict__ Wk,
    const float* __restrict__ Wv)
{
    __shared__ float sx[16 * Cc];
    const int tid = threadIdx.x;
    const long rowbase = (long)blockIdx.x * 16;

    // Stage 16 rows of x: 16*384 = 6144 floats = 1536 float4, 6 per thread.
    {
        const float4* x4 = (const float4*)(x + rowbase * Cc);
        float4* sx4 = (float4*)sx;
        #pragma unroll
        for (int i = 0; i < 6; i++)
            sx4[tid + i * 256] = x4[tid + i * 256];
    }
    __syncthreads();

    const int h  = tid & 63;
    const int r0 = (tid >> 6) * 4;   // warp-uniform

    float aq[4] = {0.f, 0.f, 0.f, 0.f};
    float ak[4] = {0.f, 0.f, 0.f, 0.f};
    float av[4] = {0.f, 0.f, 0.f, 0.f};

    #pragma unroll 4
    for (int kk = 0; kk < Cc; kk++) {
        const float wq = Wq[kk * Hh + h];
        const float wk = Wk[kk * Hh + h];
        const float wv = Wv[kk * Hh + h];
        #pragma unroll
        for (int i = 0; i < 4; i++) {
            const float xv = sx[(r0 + i) * Cc + kk];   // warp-broadcast LDS
            aq[i] = fmaf(xv, wq, aq[i]);
            ak[i] = fmaf(xv, wk, ak[i]);
            av[i] = fmaf(xv, wv, av[i]);
        }
    }

    #pragma unroll
    for (int i = 0; i < 4; i++) {
        const long o = (rowbase + r0 + i) * Hh + h;
        g_q[o] = aq[i];
        g_k[o] = ak[i];
        g_v[o] = av[i];
    }
}

// ---------------------------------------------------------------------------
// Kernel 2: causal attention, one block per batch element.
// K and V tiles (64 KB each) staged in dynamic smem (128 KB).
// One thread per query row; q[64] and o[64] live in registers.
// Online softmax with rescale-only-on-new-max (rescale fires ~ln(T) times).
// All smem reads in the j-loop are warp-uniform float4 broadcasts.
// ---------------------------------------------------------------------------
extern __shared__ float attn_smem[];

__global__ __launch_bounds__(256) void attn_kernel(float* __restrict__ out)
{
    float* sk = attn_smem;            // [T][H]
    float* sv = attn_smem + Tt * Hh;  // [T][H]

    const int b   = blockIdx.x;
    const int tid = threadIdx.x;

    // Stage K and V for this batch: 2 * 4096 float4, 16 each per thread.
    {
        const float4* gk4 = (const float4*)(g_k + (long)b * Tt * Hh);
        const float4* gv4 = (const float4*)(g_v + (long)b * Tt * Hh);
        float4* sk4 = (float4*)sk;
        float4* sv4 = (float4*)sv;
        #pragma unroll
        for (int i = 0; i < 16; i++) {
            sk4[tid + i * 256] = gk4[tid + i * 256];
            sv4[tid + i * 256] = gv4[tid + i * 256];
        }
    }
    __syncthreads();

    const int r = tid;  // query row

    // Load this thread's q row into registers.
    float4 q[16];
    {
        const float4* gq4 = (const float4*)(g_q + ((long)b * Tt + r) * Hh);
        #pragma unroll
        for (int i = 0; i < 16; i++) q[i] = gq4[i];
    }

    float o[Hh];
    #pragma unroll
    for (int i = 0; i < Hh; i++) o[i] = 0.f;

    float m = -1e30f;
    float l = 0.f;
    const float scale = rsqrtf((float)Cc);   // NOTE: C^-0.5 (384), per reference

    for (int j = 0; j <= r; j++) {
        // s = q . k_j  (4 independent accumulator chains)
        const float4* kj = (const float4*)(sk + j * Hh);
        float s0 = 0.f, s1 = 0.f, s2 = 0.f, s3 = 0.f;
        #pragma unroll
        for (int i = 0; i < 16; i++) {
            const float4 kv = kj[i];
            const float4 qi = q[i];
            s0 = fmaf(qi.x, kv.x, s0);
            s1 = fmaf(qi.y, kv.y, s1);
            s2 = fmaf(qi.z, kv.z, s2);
            s3 = fmaf(qi.w, kv.w, s3);
        }
        const float s = ((s0 + s1) + (s2 + s3)) * scale;

        float p;
        if (s > m) {
            // New max: rescale running state. Rare (~ln T per thread).
            const float corr = __expf(m - s);   // first iter: exp(-huge) = 0
            l *= corr;
            #pragma unroll
            for (int i = 0; i < Hh; i++) o[i] *= corr;
            m = s;
            p = 1.0f;
        } else {
            p = __expf(s - m);
        }
        l += p;

        const float4* vj = (const float4*)(sv + j * Hh);
        #pragma unroll
        for (int i = 0; i < 16; i++) {
            const float4 vv = vj[i];
            o[i * 4 + 0] = fmaf(p, vv.x, o[i * 4 + 0]);
            o[i * 4 + 1] = fmaf(p, vv.y, o[i * 4 + 1]);
            o[i * 4 + 2] = fmaf(p, vv.z, o[i * 4 + 2]);
            o[i * 4 + 3] = fmaf(p, vv.w, o[i * 4 + 3]);
        }
    }

    const float inv = 1.0f / l;
    float4* out4 = (float4*)(out + ((long)b * Tt + r) * Hh);
    #pragma unroll
    for (int i = 0; i < 16; i++) {
        out4[i] = make_float4(o[i * 4 + 0] * inv,
                              o[i * 4 + 1] * inv,
                              o[i * 4 + 2] * inv,
                              o[i * 4 + 3] * inv);
    }
}

// ---------------------------------------------------------------------------
// Launch
// ---------------------------------------------------------------------------
extern "C" void kernel_launch(void* const* d_in, const int* in_sizes, int n_in,
                              void* d_out, int out_size)
{
    const float* x  = (const float*)d_in[0];
    const float* Wq = (const float*)d_in[1];
    const float* Wk = (const float*)d_in[2];
    const float* Wv = (const float*)d_in[3];
    float* out = (float*)d_out;

    (void)in_sizes; (void)n_in; (void)out_size;

    const int attn_smem_bytes = 2 * Tt * Hh * (int)sizeof(float);  // 128 KB
    cudaFuncSetAttribute(attn_kernel,
                         cudaFuncAttributeMaxDynamicSharedMemorySize,
                         attn_smem_bytes);

    proj_kernel<<<BT / 16, 256>>>(x, Wq, Wk, Wv);
    attn_kernel<<<Bb, 256, attn_smem_bytes>>>(out);
}